// round 2
// baseline (speedup 1.0000x reference)
#include <cuda_runtime.h>
#include <math.h>

// ============================================================================
// conv1_max_embedding: feats[N,256] @ Wc[256,512] -> segment_max over batch_idx
//   -> fc1 [512,1024] -> BN(train) -> relu -> fc2 [1024,256] -> out [64,256]
//
// Strategy (fp32, FFMA2 packed):
//   1. counting sort of point indices by batch (so each GEMM tile = 1 segment)
//   2. fused GEMM + in-register segment max + atomicMax-on-float epilogue
//   3. tiny MLP tail kernels
// ============================================================================

#define NB 64          // batch clouds
#define C_IN 256
#define C_CONV 512
#define D1 1024
#define D2 256
#define BM 128
#define BN 128
#define BK 16
#define MAXN 500032
#define MAXTILES 4160

__device__ int   g_count[NB];
__device__ int   g_base[NB];
__device__ int   g_cursor[NB];
__device__ int   g_ntiles;
__device__ int   g_tile_seg[MAXTILES];
__device__ int   g_tile_row[MAXTILES];
__device__ int   g_tile_nrows[MAXTILES];
__device__ int   g_perm[MAXN];
__device__ float g_pooled[NB * C_CONV];
__device__ float g_h[NB * D1];
__device__ float g_hn[NB * D1];

// ---------------------------------------------------------------------------
// helpers
// ---------------------------------------------------------------------------
__device__ __forceinline__ void atomicMaxF(float* addr, float val) {
    if (val >= 0.0f) atomicMax((int*)addr, __float_as_int(val));
    else             atomicMin((unsigned int*)addr, __float_as_uint(val));
}

__device__ __forceinline__ unsigned long long dup2(float v) {
    unsigned int u = __float_as_uint(v);
    return ((unsigned long long)u << 32) | (unsigned long long)u;
}

__device__ __forceinline__ void fma2(unsigned long long& d,
                                     unsigned long long a,
                                     unsigned long long b) {
    asm("fma.rn.f32x2 %0, %1, %2, %0;" : "+l"(d) : "l"(a), "l"(b));
}

__device__ __forceinline__ float lo32(unsigned long long v) {
    return __uint_as_float((unsigned int)v);
}
__device__ __forceinline__ float hi32(unsigned long long v) {
    return __uint_as_float((unsigned int)(v >> 32));
}

// ---------------------------------------------------------------------------
// 0. init: pooled = -inf, counters = 0   (must run every graph replay)
// ---------------------------------------------------------------------------
__global__ void k_init() {
    int i = blockIdx.x * blockDim.x + threadIdx.x;
    if (i < NB * C_CONV) g_pooled[i] = __int_as_float(0xff800000);
    if (i < NB) g_count[i] = 0;
}

// ---------------------------------------------------------------------------
// 1. histogram of batch_idx
// ---------------------------------------------------------------------------
__global__ void k_hist(const int* __restrict__ bidx, int N) {
    __shared__ int lc[NB];
    int t = threadIdx.x;
    if (t < NB) lc[t] = 0;
    __syncthreads();
    int i = blockIdx.x * blockDim.x + t;
    if (i < N) atomicAdd(&lc[bidx[i]], 1);
    __syncthreads();
    if (t < NB && lc[t]) atomicAdd(&g_count[t], lc[t]);
}

// ---------------------------------------------------------------------------
// 2. prefix scan + tile table
// ---------------------------------------------------------------------------
__global__ void k_scan() {
    __shared__ int cnt[NB], sbase[NB], stb[NB];
    int t = threadIdx.x;  // 64 threads
    cnt[t] = g_count[t];
    __syncthreads();
    if (t == 0) {
        int acc = 0, ta = 0;
        for (int s = 0; s < NB; s++) {
            sbase[s] = acc; acc += cnt[s];
            stb[s] = ta;    ta += (cnt[s] + BM - 1) >> 7;
        }
        g_ntiles = ta;
    }
    __syncthreads();
    g_base[t]   = sbase[t];
    g_cursor[t] = sbase[t];
    int nt = (cnt[t] + BM - 1) >> 7;
    for (int i = 0; i < nt; i++) {
        int id = stb[t] + i;
        g_tile_seg[id]   = t;
        g_tile_row[id]   = sbase[t] + i * BM;
        g_tile_nrows[id] = min(BM, cnt[t] - i * BM);
    }
}

// ---------------------------------------------------------------------------
// 3. scatter: block-aggregated counting-sort write of permutation
// ---------------------------------------------------------------------------
__global__ void k_scatter(const int* __restrict__ bidx, int N) {
    __shared__ int lc[NB];
    __shared__ int lbase[NB];
    int t = threadIdx.x;
    if (t < NB) lc[t] = 0;
    __syncthreads();
    int i = blockIdx.x * blockDim.x + t;
    int b = 0, rank = 0;
    if (i < N) {
        b = bidx[i];
        rank = atomicAdd(&lc[b], 1);
    }
    __syncthreads();
    if (t < NB && lc[t] > 0) lbase[t] = atomicAdd(&g_cursor[t], lc[t]);
    __syncthreads();
    if (i < N) g_perm[lbase[b] + rank] = i;
}

// ---------------------------------------------------------------------------
// 4. fused GEMM (feats @ Wc) + per-segment running max epilogue
//    BM=128 x BN=128 x BK=16, 256 threads, 8x8 per thread via fma.rn.f32x2
//    smem: As2[k][row] = (a,a) duplicated;  Bs2[k][m*16+tx] = (w[c], w[c+16])
// ---------------------------------------------------------------------------
__global__ void __launch_bounds__(256, 2)
k_gemm(const float* __restrict__ feats, const float* __restrict__ Wc,
       const float* __restrict__ bc) {
    int tile = blockIdx.x;
    if (tile >= g_ntiles) return;
    int seg      = g_tile_seg[tile];
    int rowstart = g_tile_row[tile];
    int nrows    = g_tile_nrows[tile];
    int n0       = blockIdx.y * BN;

    int tid = threadIdx.x;
    int tx = tid & 15;       // column group
    int ty = tid >> 4;       // row group

    __shared__ unsigned long long As2[BK * BM];  // 16 KB
    __shared__ unsigned long long Bs2[BK * 64];  //  8 KB

    // ---- A load mapping: 2 threads per row, 8 k's each
    int lr = tid >> 1;                 // 0..127 local row
    int lh = tid & 1;                  // which 8-k half
    int lsrc = lr < nrows ? lr : (nrows - 1);   // clamp: dup last valid row
    int grow = g_perm[rowstart + lsrc];
    const float* arow = feats + (size_t)grow * C_IN;

    // ---- B load mapping: 16 threads per k-row, 8 cols each
    int bkr = tid >> 4;                // 0..15 k row
    int bl  = tid & 15;                // col group of 8

    // prefetch k-tile 0
    float4 a0 = *(const float4*)(arow + lh * 8);
    float4 a1 = *(const float4*)(arow + lh * 8 + 4);
    const float* bptr = Wc + (size_t)bkr * C_CONV + n0 + bl * 8;
    float4 b0 = *(const float4*)(bptr);
    float4 b1 = *(const float4*)(bptr + 4);

    unsigned long long acc[8][4];
#pragma unroll
    for (int r = 0; r < 8; r++)
#pragma unroll
        for (int m = 0; m < 4; m++) acc[r][m] = 0ull;

    const int NKT = C_IN / BK;  // 16
    for (int kt = 0; kt < NKT; kt++) {
        __syncthreads();
        // STS A (duplicated lanes)
        {
            float av[8] = {a0.x, a0.y, a0.z, a0.w, a1.x, a1.y, a1.z, a1.w};
#pragma unroll
            for (int i = 0; i < 8; i++)
                As2[(lh * 8 + i) * BM + lr] = dup2(av[i]);
        }
        // STS B: col c (local) -> Bs2 float addr (bkr*64 + m*16 + txc)*2 + s
        {
            float bv[8] = {b0.x, b0.y, b0.z, b0.w, b1.x, b1.y, b1.z, b1.w};
            float* Bf = (float*)Bs2;
#pragma unroll
            for (int j = 0; j < 8; j++) {
                int c = bl * 8 + j;
                int q = c >> 4, txc = c & 15;
                int m = q >> 1, s = q & 1;
                Bf[(bkr * 64 + m * 16 + txc) * 2 + s] = bv[j];
            }
        }
        __syncthreads();
        // prefetch next k-tile (overlaps with compute below)
        if (kt + 1 < NKT) {
            const float* an = arow + (kt + 1) * BK + lh * 8;
            a0 = *(const float4*)(an);
            a1 = *(const float4*)(an + 4);
            const float* bn = Wc + (size_t)((kt + 1) * BK + bkr) * C_CONV + n0 + bl * 8;
            b0 = *(const float4*)(bn);
            b1 = *(const float4*)(bn + 4);
        }
        // compute 16 kk steps
#pragma unroll
        for (int kk = 0; kk < BK; kk++) {
            unsigned long long aa[8];
#pragma unroll
            for (int i = 0; i < 4; i++) {
                ulonglong2 t2 = *(const ulonglong2*)&As2[kk * BM + ty * 8 + 2 * i];
                aa[2 * i]     = t2.x;
                aa[2 * i + 1] = t2.y;
            }
            unsigned long long bb[4];
#pragma unroll
            for (int m = 0; m < 4; m++) bb[m] = Bs2[kk * 64 + m * 16 + tx];
#pragma unroll
            for (int r = 0; r < 8; r++)
#pragma unroll
                for (int m = 0; m < 4; m++) fma2(acc[r][m], aa[r], bb[m]);
        }
    }

    // ---- epilogue: per-thread max over its 8 rows (invalid rows are
    //      duplicates of a valid row of the same segment -> harmless for max)
    float cmax[4][2];
#pragma unroll
    for (int m = 0; m < 4; m++) {
        float mlo = lo32(acc[0][m]), mhi = hi32(acc[0][m]);
#pragma unroll
        for (int r = 1; r < 8; r++) {
            mlo = fmaxf(mlo, lo32(acc[r][m]));
            mhi = fmaxf(mhi, hi32(acc[r][m]));
        }
        cmax[m][0] = mlo;  // col tx + 32m
        cmax[m][1] = mhi;  // col tx + 32m + 16
    }
    __syncthreads();
    float* red = (float*)As2;  // 16 ty-groups x 128 cols = 8KB, fits
#pragma unroll
    for (int m = 0; m < 4; m++) {
        red[ty * BN + tx + 32 * m]      = cmax[m][0];
        red[ty * BN + tx + 32 * m + 16] = cmax[m][1];
    }
    __syncthreads();
    if (tid < BN) {
        float v = red[tid];
#pragma unroll
        for (int t = 1; t < 16; t++) v = fmaxf(v, red[t * BN + tid]);
        v += bc[n0 + tid];  // bias commutes with max
        atomicMaxF(&g_pooled[seg * C_CONV + n0 + tid], v);
    }
}

// ---------------------------------------------------------------------------
// 5. small MLP GEMM  (M=64 fixed):  C = A[64,K] @ Bw[K,Nfull] + bias
//    phase 0: pooled @ W1 -> g_h     phase 1: g_hn @ W2 -> d_out
// ---------------------------------------------------------------------------
__global__ void k_mlp(const float* __restrict__ Bw, const float* __restrict__ bias,
                      int K, int Nfull, int phase, float* __restrict__ dout) {
    const float* A = (phase == 0) ? g_pooled : g_hn;
    float* C       = (phase == 0) ? g_h : dout;

    int n0  = blockIdx.x * 64;
    int tid = threadIdx.x;
    int tx = tid & 15, ty = tid >> 4;

    __shared__ float As[64][17];
    __shared__ float Bs[16][64];

    float acc[4][4];
#pragma unroll
    for (int i = 0; i < 4; i++)
#pragma unroll
        for (int j = 0; j < 4; j++) acc[i][j] = 0.0f;

    int ar = tid >> 2, ak = (tid & 3) * 4;
    int bk = tid >> 4, bc4 = (tid & 15) * 4;

    for (int k0 = 0; k0 < K; k0 += 16) {
        __syncthreads();
        float4 av = *(const float4*)(A + (size_t)ar * K + k0 + ak);
        As[ar][ak + 0] = av.x; As[ar][ak + 1] = av.y;
        As[ar][ak + 2] = av.z; As[ar][ak + 3] = av.w;
        float4 bv = *(const float4*)(Bw + (size_t)(k0 + bk) * Nfull + n0 + bc4);
        *(float4*)&Bs[bk][bc4] = bv;
        __syncthreads();
#pragma unroll
        for (int kk = 0; kk < 16; kk++) {
            float a[4], b[4];
#pragma unroll
            for (int i = 0; i < 4; i++) a[i] = As[ty * 4 + i][kk];
#pragma unroll
            for (int j = 0; j < 4; j++) b[j] = Bs[kk][tx * 4 + j];
#pragma unroll
            for (int i = 0; i < 4; i++)
#pragma unroll
                for (int j = 0; j < 4; j++) acc[i][j] = fmaf(a[i], b[j], acc[i][j]);
        }
    }
#pragma unroll
    for (int i = 0; i < 4; i++)
#pragma unroll
        for (int j = 0; j < 4; j++)
            C[(size_t)(ty * 4 + i) * Nfull + n0 + tx * 4 + j] =
                acc[i][j] + bias[n0 + tx * 4 + j];
}

// ---------------------------------------------------------------------------
// 6. BatchNorm (training stats over B=64 rows) + ReLU : g_h -> g_hn
// ---------------------------------------------------------------------------
__global__ void k_bn(const float* __restrict__ gamma, const float* __restrict__ beta) {
    int d = blockIdx.x * blockDim.x + threadIdx.x;  // 0..1023
    float v[NB];
    float s = 0.0f;
#pragma unroll
    for (int r = 0; r < NB; r++) {
        v[r] = g_h[(size_t)r * D1 + d];
        s += v[r];
    }
    float mean = s * (1.0f / NB);
    float q = 0.0f;
#pragma unroll
    for (int r = 0; r < NB; r++) {
        float df = v[r] - mean;
        q = fmaf(df, df, q);
    }
    float var = q * (1.0f / NB);
    float sc = rsqrtf(var + 1e-5f) * gamma[d];
    float bt = beta[d];
#pragma unroll
    for (int r = 0; r < NB; r++)
        g_hn[(size_t)r * D1 + d] = fmaxf(0.0f, fmaf(v[r] - mean, sc, bt));
}

// ---------------------------------------------------------------------------
// launch
// ---------------------------------------------------------------------------
extern "C" void kernel_launch(void* const* d_in, const int* in_sizes, int n_in,
                              void* d_out, int out_size) {
    const float* feats = (const float*)d_in[0];
    const int*   bidx  = (const int*)d_in[1];
    const float* Wc    = (const float*)d_in[2];
    const float* bc    = (const float*)d_in[3];
    const float* W1    = (const float*)d_in[4];
    const float* b1    = (const float*)d_in[5];
    const float* gamma = (const float*)d_in[6];
    const float* beta  = (const float*)d_in[7];
    const float* W2    = (const float*)d_in[8];
    const float* b2    = (const float*)d_in[9];
    int N = in_sizes[1];  // number of points (batch_idx element count)

    k_init<<<(NB * C_CONV + 255) / 256, 256>>>();
    k_hist<<<(N + 255) / 256, 256>>>(bidx, N);
    k_scan<<<1, 64>>>();
    k_scatter<<<(N + 255) / 256, 256>>>(bidx, N);

    int maxTiles = (N + BM - 1) / BM + NB;
    dim3 grid(maxTiles, C_CONV / BN);
    k_gemm<<<grid, 256>>>(feats, Wc, bc);

    k_mlp<<<D1 / 64, 256>>>(W1, b1, C_CONV, D1, 0, nullptr);
    k_bn<<<D1 / 256, 256>>>(gamma, beta);
    k_mlp<<<D2 / 64, 256>>>(W2, b2, D1, D2, 1, (float*)d_out);
}

// round 3
// speedup vs baseline: 3.1569x; 3.1569x over previous
#include <cuda_runtime.h>
#include <math.h>

// ============================================================================
// conv1_max_embedding: feats[N,256] @ Wc[256,512] -> segment_max over batch_idx
//   -> fc1 [512,1024] -> BN(train) -> relu -> fc2 [1024,256] -> out [64,256]
//
// Strategy R2: TF32 tensor-core GEMM (mma.sync m16n8k8) fused with segment max
//   1. counting sort of point indices by batch (each GEMM tile = 1 segment)
//   2. TF32 mma GEMM (RNA-converted inputs) + in-register max + atomicMaxF
//   3. tiny MLP tail kernels (fp32)
// ============================================================================

#define NB 64
#define C_IN 256
#define C_CONV 512
#define D1 1024
#define D2 256
#define BM 128
#define BN 128
#define BK 16
#define NIT (C_IN / BK)   // 16
#define MAXN 500032
#define MAXTILES 4160

// smem strides (words) chosen for conflict-free fragment LDS
#define SA 20     // A row stride: bank = (20*g + tig) % 32 -> permutation
#define SB 136    // B row stride: bank = (8*tig + g) % 32  -> permutation

__device__ int   g_count[NB];
__device__ int   g_base[NB];
__device__ int   g_cursor[NB];
__device__ int   g_ntiles;
__device__ int   g_tile_seg[MAXTILES];
__device__ int   g_tile_row[MAXTILES];
__device__ int   g_tile_nrows[MAXTILES];
__device__ int   g_perm[MAXN];
__device__ float g_pooled[NB * C_CONV];
__device__ float g_h[NB * D1];
__device__ float g_hn[NB * D1];

// ---------------------------------------------------------------------------
// helpers
// ---------------------------------------------------------------------------
__device__ __forceinline__ void atomicMaxF(float* addr, float val) {
    if (val >= 0.0f) atomicMax((int*)addr, __float_as_int(val));
    else             atomicMin((unsigned int*)addr, __float_as_uint(val));
}

__device__ __forceinline__ unsigned f2tf(float f) {
    unsigned r;
    asm("cvt.rna.tf32.f32 %0, %1;" : "=r"(r) : "f"(f));
    return r;
}

__device__ __forceinline__ void mma_tf32(float* c, const unsigned* a, const unsigned* b) {
    asm volatile(
        "mma.sync.aligned.m16n8k8.row.col.f32.tf32.tf32.f32 "
        "{%0,%1,%2,%3}, {%4,%5,%6,%7}, {%8,%9}, {%0,%1,%2,%3};\n"
        : "+f"(c[0]), "+f"(c[1]), "+f"(c[2]), "+f"(c[3])
        : "r"(a[0]), "r"(a[1]), "r"(a[2]), "r"(a[3]), "r"(b[0]), "r"(b[1]));
}

// ---------------------------------------------------------------------------
// 0. init (every replay)
// ---------------------------------------------------------------------------
__global__ void k_init() {
    int i = blockIdx.x * blockDim.x + threadIdx.x;
    if (i < NB * C_CONV) g_pooled[i] = __int_as_float(0xff800000);
    if (i < NB) g_count[i] = 0;
}

// ---------------------------------------------------------------------------
// 1. histogram of batch_idx
// ---------------------------------------------------------------------------
__global__ void k_hist(const int* __restrict__ bidx, int N) {
    __shared__ int lc[NB];
    int t = threadIdx.x;
    if (t < NB) lc[t] = 0;
    __syncthreads();
    int i = blockIdx.x * blockDim.x + t;
    if (i < N) atomicAdd(&lc[bidx[i]], 1);
    __syncthreads();
    if (t < NB && lc[t]) atomicAdd(&g_count[t], lc[t]);
}

// ---------------------------------------------------------------------------
// 2. prefix scan + tile table
// ---------------------------------------------------------------------------
__global__ void k_scan() {
    __shared__ int cnt[NB], sbase[NB], stb[NB];
    int t = threadIdx.x;  // 64 threads
    cnt[t] = g_count[t];
    __syncthreads();
    if (t == 0) {
        int acc = 0, ta = 0;
        for (int s = 0; s < NB; s++) {
            sbase[s] = acc; acc += cnt[s];
            stb[s] = ta;    ta += (cnt[s] + BM - 1) >> 7;
        }
        g_ntiles = ta;
    }
    __syncthreads();
    g_base[t]   = sbase[t];
    g_cursor[t] = sbase[t];
    int nt = (cnt[t] + BM - 1) >> 7;
    for (int i = 0; i < nt; i++) {
        int id = stb[t] + i;
        g_tile_seg[id]   = t;
        g_tile_row[id]   = sbase[t] + i * BM;
        g_tile_nrows[id] = min(BM, cnt[t] - i * BM);
    }
}

// ---------------------------------------------------------------------------
// 3. scatter: block-aggregated counting-sort write of permutation
// ---------------------------------------------------------------------------
__global__ void k_scatter(const int* __restrict__ bidx, int N) {
    __shared__ int lc[NB];
    __shared__ int lbase[NB];
    int t = threadIdx.x;
    if (t < NB) lc[t] = 0;
    __syncthreads();
    int i = blockIdx.x * blockDim.x + t;
    int b = 0, rank = 0;
    if (i < N) {
        b = bidx[i];
        rank = atomicAdd(&lc[b], 1);
    }
    __syncthreads();
    if (t < NB && lc[t] > 0) lbase[t] = atomicAdd(&g_cursor[t], lc[t]);
    __syncthreads();
    if (i < N) g_perm[lbase[b] + rank] = i;
}

// ---------------------------------------------------------------------------
// 4. TF32 tensor-core GEMM + per-segment max epilogue
//    BM=128 x BN=128 x BK=16, 256 threads = 8 warps (2x4), warp tile 64x32
// ---------------------------------------------------------------------------
__device__ __forceinline__ void gemm_sts(unsigned* Ab, unsigned* Bb,
                                         int r0, int ac, int kb, int c2,
                                         float4 pa0, float4 pa1,
                                         float4 pb0, float4 pb1) {
    uint4 va0 = make_uint4(f2tf(pa0.x), f2tf(pa0.y), f2tf(pa0.z), f2tf(pa0.w));
    uint4 va1 = make_uint4(f2tf(pa1.x), f2tf(pa1.y), f2tf(pa1.z), f2tf(pa1.w));
    *(uint4*)&Ab[r0 * SA + ac]        = va0;
    *(uint4*)&Ab[(r0 + 64) * SA + ac] = va1;
    uint4 vb0 = make_uint4(f2tf(pb0.x), f2tf(pb0.y), f2tf(pb0.z), f2tf(pb0.w));
    uint4 vb1 = make_uint4(f2tf(pb1.x), f2tf(pb1.y), f2tf(pb1.z), f2tf(pb1.w));
    *(uint4*)&Bb[kb * SB + c2]       = vb0;
    *(uint4*)&Bb[(kb + 8) * SB + c2] = vb1;
}

__device__ __forceinline__ void gemm_compute(const unsigned* Ab, const unsigned* Bb,
                                             float acc[4][4][4],
                                             int wm, int wn, int g, int tig) {
#pragma unroll
    for (int ks = 0; ks < 2; ks++) {
        unsigned a[4][4], bf[4][2];
#pragma unroll
        for (int mt = 0; mt < 4; mt++) {
            const unsigned* ap = &Ab[(wm * 64 + mt * 16 + g) * SA + ks * 8 + tig];
            a[mt][0] = ap[0];
            a[mt][1] = ap[8 * SA];
            a[mt][2] = ap[4];
            a[mt][3] = ap[8 * SA + 4];
        }
#pragma unroll
        for (int nt = 0; nt < 4; nt++) {
            const unsigned* bp = &Bb[(ks * 8 + tig) * SB + wn * 32 + nt * 8 + g];
            bf[nt][0] = bp[0];
            bf[nt][1] = bp[4 * SB];
        }
#pragma unroll
        for (int mt = 0; mt < 4; mt++)
#pragma unroll
            for (int nt = 0; nt < 4; nt++)
                mma_tf32(acc[mt][nt], a[mt], bf[nt]);
    }
}

__global__ void __launch_bounds__(256, 2)
k_gemm(const float* __restrict__ feats, const float* __restrict__ Wc,
       const float* __restrict__ bc) {
    int tile = blockIdx.x;
    if (tile >= g_ntiles) return;
    int seg      = g_tile_seg[tile];
    int rowstart = g_tile_row[tile];
    int nrows    = g_tile_nrows[tile];
    int n0       = blockIdx.y * BN;

    int tid  = threadIdx.x;
    int lane = tid & 31, wid = tid >> 5;
    int wm = wid & 1, wn = wid >> 1;     // 2 x 4 warp grid
    int g = lane >> 2, tig = lane & 3;

    __shared__ unsigned As[2][BM * SA];  // 2 x 10240 B
    __shared__ unsigned Bs[2][BK * SB];  // 2 x  8704 B

    // ---- global A: thread -> rows r0, r0+64 ; 4-col slab ac
    int r0 = tid >> 2;
    int ac = (tid & 3) << 2;
    const float* arow0 =
        feats + (size_t)g_perm[rowstart + min(r0, nrows - 1)] * C_IN + ac;
    const float* arow1 =
        feats + (size_t)g_perm[rowstart + min(r0 + 64, nrows - 1)] * C_IN + ac;
    // ---- global B: thread -> k rows kb, kb+8 ; 4-col slab c2
    int kb = tid >> 5;
    int c2 = (tid & 31) << 2;
    const float* bbase = Wc + (size_t)kb * C_CONV + n0 + c2;

    float acc[4][4][4];
#pragma unroll
    for (int mt = 0; mt < 4; mt++)
#pragma unroll
        for (int nt = 0; nt < 4; nt++)
#pragma unroll
            for (int r = 0; r < 4; r++) acc[mt][nt][r] = 0.0f;

    // ---- iter 0 load + store
    float4 pa0 = *(const float4*)(arow0);
    float4 pa1 = *(const float4*)(arow1);
    float4 pb0 = *(const float4*)(bbase);
    float4 pb1 = *(const float4*)(bbase + 8 * C_CONV);
    gemm_sts(As[0], Bs[0], r0, ac, kb, c2, pa0, pa1, pb0, pb1);
    __syncthreads();

    int buf = 0;
    for (int kt = 0; kt < NIT - 1; kt++) {
        // prefetch next k-slab
        pa0 = *(const float4*)(arow0 + (kt + 1) * BK);
        pa1 = *(const float4*)(arow1 + (kt + 1) * BK);
        pb0 = *(const float4*)(bbase + (size_t)(kt + 1) * BK * C_CONV);
        pb1 = *(const float4*)(bbase + (size_t)((kt + 1) * BK + 8) * C_CONV);

        gemm_compute(As[buf], Bs[buf], acc, wm, wn, g, tig);

        gemm_sts(As[buf ^ 1], Bs[buf ^ 1], r0, ac, kb, c2, pa0, pa1, pb0, pb1);
        __syncthreads();
        buf ^= 1;
    }
    gemm_compute(As[buf], Bs[buf], acc, wm, wn, g, tig);

    // ---- epilogue: max over rows (invalid rows are dups of valid -> harmless)
    float vmax[4][2];
#pragma unroll
    for (int nt = 0; nt < 4; nt++) {
        float m0 = fmaxf(acc[0][nt][0], acc[0][nt][2]);
        float m1 = fmaxf(acc[0][nt][1], acc[0][nt][3]);
#pragma unroll
        for (int mt = 1; mt < 4; mt++) {
            m0 = fmaxf(m0, fmaxf(acc[mt][nt][0], acc[mt][nt][2]));
            m1 = fmaxf(m1, fmaxf(acc[mt][nt][1], acc[mt][nt][3]));
        }
        vmax[nt][0] = m0;
        vmax[nt][1] = m1;
    }
    // reduce across the 8 g-lanes sharing each column (lane = g*4 + tig)
#pragma unroll
    for (int off = 4; off <= 16; off <<= 1) {
#pragma unroll
        for (int nt = 0; nt < 4; nt++) {
#pragma unroll
            for (int s = 0; s < 2; s++)
                vmax[nt][s] = fmaxf(vmax[nt][s],
                                    __shfl_xor_sync(0xffffffffu, vmax[nt][s], off));
        }
    }
    if (lane < 4) {  // g == 0, tig == lane
#pragma unroll
        for (int nt = 0; nt < 4; nt++) {
#pragma unroll
            for (int s = 0; s < 2; s++) {
                int col = wn * 32 + nt * 8 + 2 * lane + s;
                float v = vmax[nt][s] + bc[n0 + col];
                atomicMaxF(&g_pooled[seg * C_CONV + n0 + col], v);
            }
        }
    }
}

// ---------------------------------------------------------------------------
// 5. small MLP GEMM  (M=64 fixed):  C = A[64,K] @ Bw[K,Nfull] + bias
// ---------------------------------------------------------------------------
__global__ void k_mlp(const float* __restrict__ Bw, const float* __restrict__ bias,
                      int K, int Nfull, int phase, float* __restrict__ dout) {
    const float* A = (phase == 0) ? g_pooled : g_hn;
    float* C       = (phase == 0) ? g_h : dout;

    int n0  = blockIdx.x * 64;
    int tid = threadIdx.x;
    int tx = tid & 15, ty = tid >> 4;

    __shared__ float As[64][17];
    __shared__ float Bs[16][64];

    float acc[4][4];
#pragma unroll
    for (int i = 0; i < 4; i++)
#pragma unroll
        for (int j = 0; j < 4; j++) acc[i][j] = 0.0f;

    int ar = tid >> 2, ak = (tid & 3) * 4;
    int bk = tid >> 4, bc4 = (tid & 15) * 4;

    for (int k0 = 0; k0 < K; k0 += 16) {
        __syncthreads();
        float4 av = *(const float4*)(A + (size_t)ar * K + k0 + ak);
        As[ar][ak + 0] = av.x; As[ar][ak + 1] = av.y;
        As[ar][ak + 2] = av.z; As[ar][ak + 3] = av.w;
        float4 bv = *(const float4*)(Bw + (size_t)(k0 + bk) * Nfull + n0 + bc4);
        *(float4*)&Bs[bk][bc4] = bv;
        __syncthreads();
#pragma unroll
        for (int kk = 0; kk < 16; kk++) {
            float a[4], b[4];
#pragma unroll
            for (int i = 0; i < 4; i++) a[i] = As[ty * 4 + i][kk];
#pragma unroll
            for (int j = 0; j < 4; j++) b[j] = Bs[kk][tx * 4 + j];
#pragma unroll
            for (int i = 0; i < 4; i++)
#pragma unroll
                for (int j = 0; j < 4; j++) acc[i][j] = fmaf(a[i], b[j], acc[i][j]);
        }
    }
#pragma unroll
    for (int i = 0; i < 4; i++)
#pragma unroll
        for (int j = 0; j < 4; j++)
            C[(size_t)(ty * 4 + i) * Nfull + n0 + tx * 4 + j] =
                acc[i][j] + bias[n0 + tx * 4 + j];
}

// ---------------------------------------------------------------------------
// 6. BatchNorm (training stats over B=64 rows) + ReLU : g_h -> g_hn
// ---------------------------------------------------------------------------
__global__ void k_bn(const float* __restrict__ gamma, const float* __restrict__ beta) {
    int d = blockIdx.x * blockDim.x + threadIdx.x;  // 0..1023
    float v[NB];
    float s = 0.0f;
#pragma unroll
    for (int r = 0; r < NB; r++) {
        v[r] = g_h[(size_t)r * D1 + d];
        s += v[r];
    }
    float mean = s * (1.0f / NB);
    float q = 0.0f;
#pragma unroll
    for (int r = 0; r < NB; r++) {
        float df = v[r] - mean;
        q = fmaf(df, df, q);
    }
    float var = q * (1.0f / NB);
    float sc = rsqrtf(var + 1e-5f) * gamma[d];
    float bt = beta[d];
#pragma unroll
    for (int r = 0; r < NB; r++)
        g_hn[(size_t)r * D1 + d] = fmaxf(0.0f, fmaf(v[r] - mean, sc, bt));
}

// ---------------------------------------------------------------------------
// launch
// ---------------------------------------------------------------------------
extern "C" void kernel_launch(void* const* d_in, const int* in_sizes, int n_in,
                              void* d_out, int out_size) {
    const float* feats = (const float*)d_in[0];
    const int*   bidx  = (const int*)d_in[1];
    const float* Wc    = (const float*)d_in[2];
    const float* bc    = (const float*)d_in[3];
    const float* W1    = (const float*)d_in[4];
    const float* b1    = (const float*)d_in[5];
    const float* gamma = (const float*)d_in[6];
    const float* beta  = (const float*)d_in[7];
    const float* W2    = (const float*)d_in[8];
    const float* b2    = (const float*)d_in[9];
    int N = in_sizes[1];  // number of points (batch_idx element count)

    k_init<<<(NB * C_CONV + 255) / 256, 256>>>();
    k_hist<<<(N + 255) / 256, 256>>>(bidx, N);
    k_scan<<<1, 64>>>();
    k_scatter<<<(N + 255) / 256, 256>>>(bidx, N);

    int maxTiles = (N + BM - 1) / BM + NB;
    dim3 grid(maxTiles, C_CONV / BN);
    k_gemm<<<grid, 256>>>(feats, Wc, bc);

    k_mlp<<<D1 / 64, 256>>>(W1, b1, C_CONV, D1, 0, nullptr);
    k_bn<<<D1 / 256, 256>>>(gamma, beta);
    k_mlp<<<D2 / 64, 256>>>(W2, b2, D1, D2, 1, (float*)d_out);
}

// round 6
// speedup vs baseline: 3.3746x; 1.0690x over previous
#include <cuda_runtime.h>
#include <cuda_fp16.h>
#include <math.h>
#include <stdint.h>

// ============================================================================
// conv1_max_embedding: feats[N,256] @ Wc[256,512] -> segment_max over batch_idx
//   -> fc1 [512,1024] -> BN(train) -> relu -> fc2 [1024,256] -> out [64,256]
//
// Strategy R6: FP16 mma.sync (m16n8k16, fp32 accum) — same 10-bit mantissa as
// the passing TF32 kernel, 2x the tensor rate. tcgen05 is unavailable:
// harness compiles via compute_100 (no 'a'), which rejects tcgen05.
//   1. counting sort of point indices by batch (each GEMM tile = 1 segment)
//   2. fp16 ldmatrix GEMM + in-register max + atomicMaxF epilogue
//   3. tiny MLP tail kernels (fp32)
// ============================================================================

#define NB 64
#define C_IN 256
#define C_CONV 512
#define D1 1024
#define D2 256
#define BM 128
#define BN 128
#define BK 32            // k per smem buffer (2 mma k-steps)
#define NKT (C_IN / BK)  // 8
#define MAXN 500032
#define MAXTILES 4160

#define A_STRIDE 80      // bytes per A smem row (32 halves=64B, padded to 80)
#define B_STRIDE 256     // bytes per B smem row (128 halves)

__device__ int   g_count[NB];
__device__ int   g_cursor[NB];
__device__ int   g_ntiles;
__device__ int   g_tile_seg[MAXTILES];
__device__ int   g_tile_row[MAXTILES];
__device__ int   g_tile_nrows[MAXTILES];
__device__ int   g_perm[MAXN];
__device__ float g_pooled[NB * C_CONV];
__device__ float g_h[NB * D1];
__device__ float g_hn[NB * D1];

// ---------------------------------------------------------------------------
// helpers
// ---------------------------------------------------------------------------
__device__ __forceinline__ void atomicMaxF(float* addr, float val) {
    if (val >= 0.0f) atomicMax((int*)addr, __float_as_int(val));
    else             atomicMin((unsigned int*)addr, __float_as_uint(val));
}

__device__ __forceinline__ uint32_t packh2(float lo, float hi) {
    __half2 h = __floats2half2_rn(lo, hi);
    return *(uint32_t*)&h;
}

__device__ __forceinline__ void ldmA(uint32_t* r, uint32_t addr) {
    asm volatile("ldmatrix.sync.aligned.m8n8.x4.shared.b16 {%0,%1,%2,%3}, [%4];"
                 : "=r"(r[0]), "=r"(r[1]), "=r"(r[2]), "=r"(r[3]) : "r"(addr));
}
__device__ __forceinline__ void ldmBT(uint32_t* r, uint32_t addr) {
    asm volatile("ldmatrix.sync.aligned.m8n8.x2.trans.shared.b16 {%0,%1}, [%2];"
                 : "=r"(r[0]), "=r"(r[1]) : "r"(addr));
}
__device__ __forceinline__ void mma_f16(float* c, const uint32_t* a,
                                        const uint32_t* b) {
    asm volatile(
        "mma.sync.aligned.m16n8k16.row.col.f32.f16.f16.f32 "
        "{%0,%1,%2,%3}, {%4,%5,%6,%7}, {%8,%9}, {%0,%1,%2,%3};\n"
        : "+f"(c[0]), "+f"(c[1]), "+f"(c[2]), "+f"(c[3])
        : "r"(a[0]), "r"(a[1]), "r"(a[2]), "r"(a[3]), "r"(b[0]), "r"(b[1]));
}

// ---------------------------------------------------------------------------
// 0. init (every replay)
// ---------------------------------------------------------------------------
__global__ void k_init() {
    int i = blockIdx.x * blockDim.x + threadIdx.x;
    if (i < NB * C_CONV) g_pooled[i] = __int_as_float(0xff800000);
    if (i < NB) g_count[i] = 0;
}

// ---------------------------------------------------------------------------
// 1. histogram of batch_idx
// ---------------------------------------------------------------------------
__global__ void k_hist(const int* __restrict__ bidx, int N) {
    __shared__ int lc[NB];
    int t = threadIdx.x;
    if (t < NB) lc[t] = 0;
    __syncthreads();
    int i = blockIdx.x * blockDim.x + t;
    if (i < N) atomicAdd(&lc[bidx[i]], 1);
    __syncthreads();
    if (t < NB && lc[t]) atomicAdd(&g_count[t], lc[t]);
}

// ---------------------------------------------------------------------------
// 2. prefix scan + tile table (BM = 128)
// ---------------------------------------------------------------------------
__global__ void k_scan() {
    __shared__ int cnt[NB], sbase[NB], stb[NB];
    int t = threadIdx.x;  // 64 threads
    cnt[t] = g_count[t];
    __syncthreads();
    if (t == 0) {
        int acc = 0, ta = 0;
        for (int s = 0; s < NB; s++) {
            sbase[s] = acc; acc += cnt[s];
            stb[s] = ta;    ta += (cnt[s] + BM - 1) >> 7;
        }
        g_ntiles = ta;
    }
    __syncthreads();
    g_cursor[t] = sbase[t];
    int nt = (cnt[t] + BM - 1) >> 7;
    for (int i = 0; i < nt; i++) {
        int id = stb[t] + i;
        g_tile_seg[id]   = t;
        g_tile_row[id]   = sbase[t] + i * BM;
        g_tile_nrows[id] = min(BM, cnt[t] - i * BM);
    }
}

// ---------------------------------------------------------------------------
// 3. scatter: block-aggregated counting-sort write of permutation
// ---------------------------------------------------------------------------
__global__ void k_scatter(const int* __restrict__ bidx, int N) {
    __shared__ int lc[NB];
    __shared__ int lbase[NB];
    int t = threadIdx.x;
    if (t < NB) lc[t] = 0;
    __syncthreads();
    int i = blockIdx.x * blockDim.x + t;
    int b = 0, rank = 0;
    if (i < N) {
        b = bidx[i];
        rank = atomicAdd(&lc[b], 1);
    }
    __syncthreads();
    if (t < NB && lc[t] > 0) lbase[t] = atomicAdd(&g_cursor[t], lc[t]);
    __syncthreads();
    if (i < N) g_perm[lbase[b] + rank] = i;
}

// ---------------------------------------------------------------------------
// 4. FP16 tensor-core GEMM + per-segment max epilogue
//    grid = (C_CONV/BN, tiles); 256 threads = 8 warps (2 x 4), warp 64x32
// ---------------------------------------------------------------------------
__global__ void __launch_bounds__(256, 2)
k_gemm(const float* __restrict__ feats, const float* __restrict__ Wc,
       const float* __restrict__ bc) {
    int tile = blockIdx.y;
    if (tile >= g_ntiles) return;
    int seg      = g_tile_seg[tile];
    int rowstart = g_tile_row[tile];
    int nrows    = g_tile_nrows[tile];
    int n0       = blockIdx.x * BN;

    int tid  = threadIdx.x;
    int lane = tid & 31, wid = tid >> 5;
    int wm = wid & 1, wn = wid >> 1;   // 2 x 4 warp grid

    __shared__ __align__(128) char smA[2][BM * A_STRIDE];  // 2 x 10240
    __shared__ __align__(128) char smB[2][BK * B_STRIDE];  // 2 x  8192

    // ---- A global mapping: 2 threads per row, 16 floats each
    int ar  = tid >> 1;
    int akh = tid & 1;  // k half (halves 0-15 / 16-31)
    const float* arow =
        feats + (size_t)g_perm[rowstart + min(ar, nrows - 1)] * C_IN + akh * 16;
    // ---- B global mapping: 8 threads per k-row, 16 floats each
    int bk  = tid >> 3;        // 0..31 k row within buffer
    int bnc = tid & 7;         // 16-float slab
    const float* bbase = Wc + (size_t)bk * C_CONV + n0 + bnc * 16;

    float acc[4][4][4];
#pragma unroll
    for (int mt = 0; mt < 4; mt++)
#pragma unroll
        for (int nt = 0; nt < 4; nt++)
#pragma unroll
            for (int r = 0; r < 4; r++) acc[mt][nt][r] = 0.0f;

    uint32_t sa[8], sb[8];

    // ---- stage + store for k-tile 0
    {
        const float4* ap = (const float4*)(arow);
        float4 a0 = ap[0], a1 = ap[1], a2 = ap[2], a3 = ap[3];
        sa[0] = packh2(a0.x, a0.y); sa[1] = packh2(a0.z, a0.w);
        sa[2] = packh2(a1.x, a1.y); sa[3] = packh2(a1.z, a1.w);
        sa[4] = packh2(a2.x, a2.y); sa[5] = packh2(a2.z, a2.w);
        sa[6] = packh2(a3.x, a3.y); sa[7] = packh2(a3.z, a3.w);
        const float4* bp = (const float4*)(bbase);
        float4 b0 = bp[0], b1 = bp[1], b2 = bp[2], b3 = bp[3];
        sb[0] = packh2(b0.x, b0.y); sb[1] = packh2(b0.z, b0.w);
        sb[2] = packh2(b1.x, b1.y); sb[3] = packh2(b1.z, b1.w);
        sb[4] = packh2(b2.x, b2.y); sb[5] = packh2(b2.z, b2.w);
        sb[6] = packh2(b3.x, b3.y); sb[7] = packh2(b3.z, b3.w);
    }
    {
        char* ad = smA[0] + ar * A_STRIDE + akh * 32;
        *(uint4*)(ad)      = make_uint4(sa[0], sa[1], sa[2], sa[3]);
        *(uint4*)(ad + 16) = make_uint4(sa[4], sa[5], sa[6], sa[7]);
        int c0 = (bnc * 2)     ^ (bk & 7);
        int c1 = (bnc * 2 + 1) ^ (bk & 7);
        char* bd = smB[0] + bk * B_STRIDE;
        *(uint4*)(bd + c0 * 16) = make_uint4(sb[0], sb[1], sb[2], sb[3]);
        *(uint4*)(bd + c1 * 16) = make_uint4(sb[4], sb[5], sb[6], sb[7]);
    }
    __syncthreads();

    // ldmatrix lane addressing (constant per thread)
    int asub = lane >> 3, al7 = lane & 7;
    int arow_frag_base = (asub & 1) * 8 + al7;     // + wm*64 + mt*16
    int akoff = (asub >> 1) * 16;                  // + ks*32
    int bl15 = lane & 15;

    for (int kt = 0; kt < NKT; kt++) {
        int buf = kt & 1;
        // prefetch next k-tile into registers (converted)
        if (kt + 1 < NKT) {
            const float4* ap = (const float4*)(arow + (kt + 1) * BK);
            float4 a0 = ap[0], a1 = ap[1], a2 = ap[2], a3 = ap[3];
            sa[0] = packh2(a0.x, a0.y); sa[1] = packh2(a0.z, a0.w);
            sa[2] = packh2(a1.x, a1.y); sa[3] = packh2(a1.z, a1.w);
            sa[4] = packh2(a2.x, a2.y); sa[5] = packh2(a2.z, a2.w);
            sa[6] = packh2(a3.x, a3.y); sa[7] = packh2(a3.z, a3.w);
            const float4* bp =
                (const float4*)(bbase + (size_t)(kt + 1) * BK * C_CONV);
            float4 b0 = bp[0], b1 = bp[1], b2 = bp[2], b3 = bp[3];
            sb[0] = packh2(b0.x, b0.y); sb[1] = packh2(b0.z, b0.w);
            sb[2] = packh2(b1.x, b1.y); sb[3] = packh2(b1.z, b1.w);
            sb[4] = packh2(b2.x, b2.y); sb[5] = packh2(b2.z, b2.w);
            sb[6] = packh2(b3.x, b3.y); sb[7] = packh2(b3.z, b3.w);
        }

        // ---- compute on current buffer: 2 k-steps of 16
        uint32_t aB = (uint32_t)__cvta_generic_to_shared(smA[buf]);
        uint32_t bB = (uint32_t)__cvta_generic_to_shared(smB[buf]);
#pragma unroll
        for (int ks = 0; ks < 2; ks++) {
            uint32_t af[4][4];
#pragma unroll
            for (int mt = 0; mt < 4; mt++) {
                int row = wm * 64 + mt * 16 + arow_frag_base;
                ldmA(af[mt], aB + row * A_STRIDE + ks * 32 + akoff);
            }
            uint32_t bf[4][2];
            int krow = ks * 16 + bl15;
#pragma unroll
            for (int nt = 0; nt < 4; nt++) {
                int nf = wn * 4 + nt;
                ldmBT(bf[nt], bB + krow * B_STRIDE + ((nf ^ (krow & 7)) * 16));
            }
#pragma unroll
            for (int mt = 0; mt < 4; mt++)
#pragma unroll
                for (int nt = 0; nt < 4; nt++)
                    mma_f16(acc[mt][nt], af[mt], bf[nt]);
        }

        // ---- store prefetched tile into the other buffer
        if (kt + 1 < NKT) {
            char* ad = smA[buf ^ 1] + ar * A_STRIDE + akh * 32;
            *(uint4*)(ad)      = make_uint4(sa[0], sa[1], sa[2], sa[3]);
            *(uint4*)(ad + 16) = make_uint4(sa[4], sa[5], sa[6], sa[7]);
            int c0 = (bnc * 2)     ^ (bk & 7);
            int c1 = (bnc * 2 + 1) ^ (bk & 7);
            char* bd = smB[buf ^ 1] + bk * B_STRIDE;
            *(uint4*)(bd + c0 * 16) = make_uint4(sb[0], sb[1], sb[2], sb[3]);
            *(uint4*)(bd + c1 * 16) = make_uint4(sb[4], sb[5], sb[6], sb[7]);
            __syncthreads();
        }
    }

    // ---- epilogue: max over rows (invalid rows are dups of valid -> harmless)
    float vmax[4][2];
#pragma unroll
    for (int nt = 0; nt < 4; nt++) {
        float m0 = fmaxf(acc[0][nt][0], acc[0][nt][2]);
        float m1 = fmaxf(acc[0][nt][1], acc[0][nt][3]);
#pragma unroll
        for (int mt = 1; mt < 4; mt++) {
            m0 = fmaxf(m0, fmaxf(acc[mt][nt][0], acc[mt][nt][2]));
            m1 = fmaxf(m1, fmaxf(acc[mt][nt][1], acc[mt][nt][3]));
        }
        vmax[nt][0] = m0;
        vmax[nt][1] = m1;
    }
#pragma unroll
    for (int off = 4; off <= 16; off <<= 1) {
#pragma unroll
        for (int nt = 0; nt < 4; nt++) {
#pragma unroll
            for (int s = 0; s < 2; s++)
                vmax[nt][s] = fmaxf(vmax[nt][s],
                                    __shfl_xor_sync(0xffffffffu, vmax[nt][s], off));
        }
    }
    if (lane < 4) {  // g == 0, tig == lane
#pragma unroll
        for (int nt = 0; nt < 4; nt++) {
#pragma unroll
            for (int s = 0; s < 2; s++) {
                int col = wn * 32 + nt * 8 + 2 * lane + s;
                float v = vmax[nt][s] + bc[n0 + col];
                atomicMaxF(&g_pooled[seg * C_CONV + n0 + col], v);
            }
        }
    }
}

// ---------------------------------------------------------------------------
// 5. small MLP GEMM  (M=64 fixed):  C = A[64,K] @ Bw[K,Nfull] + bias
// ---------------------------------------------------------------------------
__global__ void k_mlp(const float* __restrict__ Bw, const float* __restrict__ bias,
                      int K, int Nfull, int phase, float* __restrict__ dout) {
    const float* A = (phase == 0) ? g_pooled : g_hn;
    float* C       = (phase == 0) ? g_h : dout;

    int n0  = blockIdx.x * 64;
    int tid = threadIdx.x;
    int tx = tid & 15, ty = tid >> 4;

    __shared__ float As[64][17];
    __shared__ float Bs[16][64];

    float acc[4][4];
#pragma unroll
    for (int i = 0; i < 4; i++)
#pragma unroll
        for (int j = 0; j < 4; j++) acc[i][j] = 0.0f;

    int ar = tid >> 2, ak = (tid & 3) * 4;
    int bk = tid >> 4, bc4 = (tid & 15) * 4;

    for (int k0 = 0; k0 < K; k0 += 16) {
        __syncthreads();
        float4 av = *(const float4*)(A + (size_t)ar * K + k0 + ak);
        As[ar][ak + 0] = av.x; As[ar][ak + 1] = av.y;
        As[ar][ak + 2] = av.z; As[ar][ak + 3] = av.w;
        float4 bv = *(const float4*)(Bw + (size_t)(k0 + bk) * Nfull + n0 + bc4);
        *(float4*)&Bs[bk][bc4] = bv;
        __syncthreads();
#pragma unroll
        for (int kk = 0; kk < 16; kk++) {
            float a[4], b[4];
#pragma unroll
            for (int i = 0; i < 4; i++) a[i] = As[ty * 4 + i][kk];
#pragma unroll
            for (int j = 0; j < 4; j++) b[j] = Bs[kk][tx * 4 + j];
#pragma unroll
            for (int i = 0; i < 4; i++)
#pragma unroll
                for (int j = 0; j < 4; j++) acc[i][j] = fmaf(a[i], b[j], acc[i][j]);
        }
    }
#pragma unroll
    for (int i = 0; i < 4; i++)
#pragma unroll
        for (int j = 0; j < 4; j++)
            C[(size_t)(ty * 4 + i) * Nfull + n0 + tx * 4 + j] =
                acc[i][j] + bias[n0 + tx * 4 + j];
}

// ---------------------------------------------------------------------------
// 6. BatchNorm (training stats over B=64 rows) + ReLU : g_h -> g_hn
// ---------------------------------------------------------------------------
__global__ void k_bn(const float* __restrict__ gamma, const float* __restrict__ beta) {
    int d = blockIdx.x * blockDim.x + threadIdx.x;  // 0..1023
    float v[NB];
    float s = 0.0f;
#pragma unroll
    for (int r = 0; r < NB; r++) {
        v[r] = g_h[(size_t)r * D1 + d];
        s += v[r];
    }
    float mean = s * (1.0f / NB);
    float q = 0.0f;
#pragma unroll
    for (int r = 0; r < NB; r++) {
        float df = v[r] - mean;
        q = fmaf(df, df, q);
    }
    float var = q * (1.0f / NB);
    float sc = rsqrtf(var + 1e-5f) * gamma[d];
    float bt = beta[d];
#pragma unroll
    for (int r = 0; r < NB; r++)
        g_hn[(size_t)r * D1 + d] = fmaxf(0.0f, fmaf(v[r] - mean, sc, bt));
}

// ---------------------------------------------------------------------------
// launch
// ---------------------------------------------------------------------------
extern "C" void kernel_launch(void* const* d_in, const int* in_sizes, int n_in,
                              void* d_out, int out_size) {
    const float* feats = (const float*)d_in[0];
    const int*   bidx  = (const int*)d_in[1];
    const float* Wc    = (const float*)d_in[2];
    const float* bc    = (const float*)d_in[3];
    const float* W1    = (const float*)d_in[4];
    const float* b1    = (const float*)d_in[5];
    const float* gamma = (const float*)d_in[6];
    const float* beta  = (const float*)d_in[7];
    const float* W2    = (const float*)d_in[8];
    const float* b2    = (const float*)d_in[9];
    int N = in_sizes[1];  // number of points (batch_idx element count)

    k_init<<<(NB * C_CONV + 255) / 256, 256>>>();
    k_hist<<<(N + 255) / 256, 256>>>(bidx, N);
    k_scan<<<1, 64>>>();
    k_scatter<<<(N + 255) / 256, 256>>>(bidx, N);

    int maxTiles = (N + BM - 1) / BM + NB;
    dim3 grid(C_CONV / BN, maxTiles);   // n-blocks fastest -> L2 reuse of feats
    k_gemm<<<grid, 256>>>(feats, Wc, bc);

    k_mlp<<<D1 / 64, 256>>>(W1, b1, C_CONV, D1, 0, nullptr);
    k_bn<<<D1 / 256, 256>>>(gamma, beta);
    k_mlp<<<D2 / 64, 256>>>(W2, b2, D1, D2, 1, (float*)d_out);
}

// round 7
// speedup vs baseline: 4.3393x; 1.2858x over previous
#include <cuda_runtime.h>
#include <cuda_fp16.h>
#include <math.h>
#include <stdint.h>

// ============================================================================
// conv1_max_embedding: feats[N,256] @ Wc[256,512] -> segment_max over batch_idx
//   -> fc1 [512,1024] -> BN(train) -> relu -> fc2 [1024,256] -> out [64,256]
//
// Strategy R7:
//   1. counting sort by batch  (tile = 1 segment)
//   2. pre-convert feats (gathered) + Wc to fp16 once
//   3. fp16 mma GEMM with cp.async double-buffer; epilogue tracks ARGMAX row
//      per (seg,col) via packed 64-bit atomicMax (value<<32 | row, deterministic)
//   4. exact fp32 recompute of the 64x512 selected dot products (kills fp16
//      error in the output values)
//   5. tiny MLP tail kernels (fp32)
// ============================================================================

#define NB 64
#define C_IN 256
#define C_CONV 512
#define D1 1024
#define D2 256
#define BM 128
#define BN 128
#define BK 32            // k per smem stage (2 mma k-steps)
#define NKT (C_IN / BK)  // 8
#define MAXN 500032
#define MAXTILES 4160

#define A_STRIDE 80      // bytes per A smem row (32 halves=64B, padded to 80)
#define B_STRIDE 256     // bytes per B smem row (128 halves)

__device__ int   g_count[NB];
__device__ int   g_cursor[NB];
__device__ int   g_ntiles;
__device__ int   g_tile_seg[MAXTILES];
__device__ int   g_tile_row[MAXTILES];
__device__ int   g_tile_nrows[MAXTILES];
__device__ int   g_perm[MAXN];
__device__ unsigned long long g_argkey[NB * C_CONV];
__device__ float g_pooled[NB * C_CONV];
__device__ float g_h[NB * D1];
__device__ float g_hn[NB * D1];
__device__ __half g_afp16[(size_t)MAXN * C_IN];   // 256 MB scratch (sorted rows)
__device__ __half g_wfp16[C_IN * C_CONV];

// ---------------------------------------------------------------------------
// helpers
// ---------------------------------------------------------------------------
__device__ __forceinline__ unsigned long long packkey(float v, int row) {
    unsigned u = __float_as_uint(v);
    u = (u & 0x80000000u) ? ~u : (u | 0x80000000u);  // order-preserving map
    return ((unsigned long long)u << 32) | (unsigned)row;
}

__device__ __forceinline__ void cpa16(uint32_t dst, const void* src) {
    asm volatile("cp.async.cg.shared.global [%0], [%1], 16;"
                 :: "r"(dst), "l"(src) : "memory");
}
__device__ __forceinline__ void cpa_commit() {
    asm volatile("cp.async.commit_group;" ::: "memory");
}
template <int N>
__device__ __forceinline__ void cpa_wait() {
    asm volatile("cp.async.wait_group %0;" :: "n"(N) : "memory");
}

__device__ __forceinline__ void ldmA(uint32_t* r, uint32_t addr) {
    asm volatile("ldmatrix.sync.aligned.m8n8.x4.shared.b16 {%0,%1,%2,%3}, [%4];"
                 : "=r"(r[0]), "=r"(r[1]), "=r"(r[2]), "=r"(r[3]) : "r"(addr));
}
__device__ __forceinline__ void ldmBT(uint32_t* r, uint32_t addr) {
    asm volatile("ldmatrix.sync.aligned.m8n8.x2.trans.shared.b16 {%0,%1}, [%2];"
                 : "=r"(r[0]), "=r"(r[1]) : "r"(addr));
}
__device__ __forceinline__ void mma_f16(float* c, const uint32_t* a,
                                        const uint32_t* b) {
    asm volatile(
        "mma.sync.aligned.m16n8k16.row.col.f32.f16.f16.f32 "
        "{%0,%1,%2,%3}, {%4,%5,%6,%7}, {%8,%9}, {%0,%1,%2,%3};\n"
        : "+f"(c[0]), "+f"(c[1]), "+f"(c[2]), "+f"(c[3])
        : "r"(a[0]), "r"(a[1]), "r"(a[2]), "r"(a[3]), "r"(b[0]), "r"(b[1]));
}

// ---------------------------------------------------------------------------
// 0. init (every replay): zero argmax keys + histogram counters
// ---------------------------------------------------------------------------
__global__ void k_init() {
    int i = blockIdx.x * blockDim.x + threadIdx.x;
    if (i < NB * C_CONV) g_argkey[i] = 0ull;
    if (i < NB) g_count[i] = 0;
}

// ---------------------------------------------------------------------------
// 1. histogram of batch_idx
// ---------------------------------------------------------------------------
__global__ void k_hist(const int* __restrict__ bidx, int N) {
    __shared__ int lc[NB];
    int t = threadIdx.x;
    if (t < NB) lc[t] = 0;
    __syncthreads();
    int i = blockIdx.x * blockDim.x + t;
    if (i < N) atomicAdd(&lc[bidx[i]], 1);
    __syncthreads();
    if (t < NB && lc[t]) atomicAdd(&g_count[t], lc[t]);
}

// ---------------------------------------------------------------------------
// 2. prefix scan + tile table (BM = 128)
// ---------------------------------------------------------------------------
__global__ void k_scan() {
    __shared__ int cnt[NB], sbase[NB], stb[NB];
    int t = threadIdx.x;  // 64 threads
    cnt[t] = g_count[t];
    __syncthreads();
    if (t == 0) {
        int acc = 0, ta = 0;
        for (int s = 0; s < NB; s++) {
            sbase[s] = acc; acc += cnt[s];
            stb[s] = ta;    ta += (cnt[s] + BM - 1) >> 7;
        }
        g_ntiles = ta;
    }
    __syncthreads();
    g_cursor[t] = sbase[t];
    int nt = (cnt[t] + BM - 1) >> 7;
    for (int i = 0; i < nt; i++) {
        int id = stb[t] + i;
        g_tile_seg[id]   = t;
        g_tile_row[id]   = sbase[t] + i * BM;
        g_tile_nrows[id] = min(BM, cnt[t] - i * BM);
    }
}

// ---------------------------------------------------------------------------
// 3. scatter: block-aggregated counting-sort write of permutation
// ---------------------------------------------------------------------------
__global__ void k_scatter(const int* __restrict__ bidx, int N) {
    __shared__ int lc[NB];
    __shared__ int lbase[NB];
    int t = threadIdx.x;
    if (t < NB) lc[t] = 0;
    __syncthreads();
    int i = blockIdx.x * blockDim.x + t;
    int b = 0, rank = 0;
    if (i < N) {
        b = bidx[i];
        rank = atomicAdd(&lc[b], 1);
    }
    __syncthreads();
    if (t < NB && lc[t] > 0) lbase[t] = atomicAdd(&g_cursor[t], lc[t]);
    __syncthreads();
    if (i < N) g_perm[lbase[b] + rank] = i;
}

// ---------------------------------------------------------------------------
// 3b. gather + convert feats rows into sorted fp16 array (1 warp per row)
// ---------------------------------------------------------------------------
__global__ void k_convert(const float* __restrict__ feats, int N) {
    int r = blockIdx.x * 8 + (threadIdx.x >> 5);
    if (r >= N) return;
    int lane = threadIdx.x & 31;
    int srow = g_perm[r];
    const float4* s = (const float4*)(feats + (size_t)srow * C_IN + lane * 8);
    float4 x = s[0], y = s[1];
    __half2 h0 = __floats2half2_rn(x.x, x.y), h1 = __floats2half2_rn(x.z, x.w);
    __half2 h2 = __floats2half2_rn(y.x, y.y), h3 = __floats2half2_rn(y.z, y.w);
    uint4 o = make_uint4(*(unsigned*)&h0, *(unsigned*)&h1,
                         *(unsigned*)&h2, *(unsigned*)&h3);
    *(uint4*)(g_afp16 + (size_t)r * C_IN + lane * 8) = o;
}

// 3c. convert Wc to fp16
__global__ void k_convw(const float* __restrict__ Wc) {
    int i = (blockIdx.x * 256 + threadIdx.x) * 8;  // 64 blocks cover 131072
    const float4* s = (const float4*)(Wc + i);
    float4 x = s[0], y = s[1];
    __half2 h0 = __floats2half2_rn(x.x, x.y), h1 = __floats2half2_rn(x.z, x.w);
    __half2 h2 = __floats2half2_rn(y.x, y.y), h3 = __floats2half2_rn(y.z, y.w);
    uint4 o = make_uint4(*(unsigned*)&h0, *(unsigned*)&h1,
                         *(unsigned*)&h2, *(unsigned*)&h3);
    *(uint4*)(g_wfp16 + i) = o;
}

// ---------------------------------------------------------------------------
// 4. FP16 tensor GEMM (cp.async double-buffer) + ARGMAX epilogue
//    grid = (C_CONV/BN, tiles); 256 threads = 8 warps (2 x 4), warp 64x32
// ---------------------------------------------------------------------------
__global__ void __launch_bounds__(256, 2)
k_gemm(const __half* __restrict__ dummy) {
    int tile = blockIdx.y;
    if (tile >= g_ntiles) return;
    int seg      = g_tile_seg[tile];
    int rowstart = g_tile_row[tile];
    int nrows    = g_tile_nrows[tile];
    int n0       = blockIdx.x * BN;

    int tid  = threadIdx.x;
    int lane = tid & 31, wid = tid >> 5;
    int wm = wid & 1, wn = wid >> 1;   // 2 x 4 warp grid

    __shared__ __align__(128) char smA[2][BM * A_STRIDE];  // 2 x 10240
    __shared__ __align__(128) char smB[2][BK * B_STRIDE];  // 2 x  8192

    // ---- A copy mapping: 2 threads per row, 16 halves (32B) each
    int ar  = tid >> 1;
    int akh = tid & 1;
    const __half* aptr =
        g_afp16 + (size_t)(rowstart + min(ar, nrows - 1)) * C_IN + akh * 16;
    uint32_t adst = (uint32_t)__cvta_generic_to_shared(smA[0]) +
                    ar * A_STRIDE + akh * 32;
    // ---- B copy mapping: 8 threads per k-row, 16 halves each (2 chunks)
    int bk  = tid >> 3;        // 0..31 k row within stage
    int bnc = tid & 7;
    const __half* bptr = g_wfp16 + (size_t)bk * C_CONV + n0 + bnc * 16;
    int c0 = (bnc * 2)     ^ (bk & 7);
    int c1 = (bnc * 2 + 1) ^ (bk & 7);
    uint32_t bdst = (uint32_t)__cvta_generic_to_shared(smB[0]) + bk * B_STRIDE;
    const uint32_t ABUF = sizeof(smA[0]);
    const uint32_t BBUF = sizeof(smB[0]);

    float acc[4][4][4];
#pragma unroll
    for (int mt = 0; mt < 4; mt++)
#pragma unroll
        for (int nt = 0; nt < 4; nt++)
#pragma unroll
            for (int r = 0; r < 4; r++) acc[mt][nt][r] = 0.0f;

    // ---- prologue: stage 0
    cpa16(adst, aptr);
    cpa16(adst + 16, aptr + 8);
    cpa16(bdst + c0 * 16, bptr);
    cpa16(bdst + c1 * 16, bptr + 8);
    cpa_commit();

    // ldmatrix lane addressing (constant per thread)
    int asub = lane >> 3, al7 = lane & 7;
    int arow_frag = (asub & 1) * 8 + al7;
    int akoff = (asub >> 1) * 16;
    int bl15 = lane & 15;
    uint32_t aB0 = (uint32_t)__cvta_generic_to_shared(smA[0]);
    uint32_t bB0 = (uint32_t)__cvta_generic_to_shared(smB[0]);

    for (int kt = 0; kt < NKT; kt++) {
        int buf = kt & 1;
        if (kt + 1 < NKT) {
            int nb = (kt + 1) & 1;
            const __half* an = aptr + (kt + 1) * BK;
            cpa16(adst + nb * ABUF, an);
            cpa16(adst + nb * ABUF + 16, an + 8);
            const __half* bn = bptr + (size_t)(kt + 1) * BK * C_CONV;
            cpa16(bdst + nb * BBUF + c0 * 16, bn);
            cpa16(bdst + nb * BBUF + c1 * 16, bn + 8);
            cpa_commit();
            cpa_wait<1>();
        } else {
            cpa_wait<0>();
        }
        __syncthreads();

        uint32_t aB = aB0 + buf * ABUF;
        uint32_t bB = bB0 + buf * BBUF;
#pragma unroll
        for (int ks = 0; ks < 2; ks++) {
            uint32_t af[4][4];
#pragma unroll
            for (int mt = 0; mt < 4; mt++) {
                int row = wm * 64 + mt * 16 + arow_frag;
                ldmA(af[mt], aB + row * A_STRIDE + ks * 32 + akoff);
            }
            uint32_t bf[4][2];
            int krow = ks * 16 + bl15;
#pragma unroll
            for (int nt = 0; nt < 4; nt++) {
                int nf = wn * 4 + nt;
                ldmBT(bf[nt], bB + krow * B_STRIDE + ((nf ^ (krow & 7)) * 16));
            }
#pragma unroll
            for (int mt = 0; mt < 4; mt++)
#pragma unroll
                for (int nt = 0; nt < 4; nt++)
                    mma_f16(acc[mt][nt], af[mt], bf[nt]);
        }
        __syncthreads();  // all warps done reading buf before it is rewritten
    }

    // ---- epilogue: ARGMAX over rows, packed-key atomicMax (deterministic)
    // acc[mt][nt][r]: row = wm*64 + mt*16 + (lane>>2) + (r>=2 ? 8 : 0)
    //                 col = wn*32 + nt*8 + (lane&3)*2 + (r&1)
    int g = lane >> 2;
    int orow[4][2];
#pragma unroll
    for (int mt = 0; mt < 4; mt++)
#pragma unroll
        for (int h = 0; h < 2; h++) {
            int lrow = wm * 64 + mt * 16 + g + h * 8;
            orow[mt][h] = g_perm[rowstart + min(lrow, nrows - 1)];
        }
#pragma unroll
    for (int nt = 0; nt < 4; nt++) {
#pragma unroll
        for (int s = 0; s < 2; s++) {
            float v = acc[0][nt][s];
            int   bi = orow[0][0];
#pragma unroll
            for (int mt = 0; mt < 4; mt++) {
#pragma unroll
                for (int h = 0; h < 2; h++) {
                    float f = acc[mt][nt][s + 2 * h];
                    int   fi = orow[mt][h];
                    if (f > v || (f == v && fi > bi)) { v = f; bi = fi; }
                }
            }
#pragma unroll
            for (int off = 4; off <= 16; off <<= 1) {
                float fv = __shfl_xor_sync(0xffffffffu, v, off);
                int   fi = __shfl_xor_sync(0xffffffffu, bi, off);
                if (fv > v || (fv == v && fi > bi)) { v = fv; bi = fi; }
            }
            if (lane < 4) {
                int col = n0 + wn * 32 + nt * 8 + lane * 2 + s;
                atomicMax(&g_argkey[seg * C_CONV + col], packkey(v, bi));
            }
        }
    }
}

// ---------------------------------------------------------------------------
// 4b. exact fp32 recompute of selected dot products (1 warp per output)
// ---------------------------------------------------------------------------
__global__ void k_exact(const float* __restrict__ feats,
                        const float* __restrict__ Wc,
                        const float* __restrict__ bcv) {
    int w = (blockIdx.x * blockDim.x + threadIdx.x) >> 5;
    if (w >= NB * C_CONV) return;
    int lane = threadIdx.x & 31;
    unsigned long long key = g_argkey[w];
    int col = w & (C_CONV - 1);
    float r;
    if (key == 0ull) {
        r = -3.0e38f;
    } else {
        int frow = (int)(unsigned)(key & 0xFFFFFFFFull);
        const float* a = feats + (size_t)frow * C_IN + lane * 8;
        float s = 0.0f;
#pragma unroll
        for (int j = 0; j < 8; j++)
            s = fmaf(a[j], Wc[(size_t)(lane * 8 + j) * C_CONV + col], s);
#pragma unroll
        for (int off = 16; off > 0; off >>= 1)
            s += __shfl_xor_sync(0xffffffffu, s, off);
        r = s + bcv[col];
    }
    if (lane == 0) g_pooled[w] = r;
}

// ---------------------------------------------------------------------------
// 5. small MLP GEMM  (M=64 fixed):  C = A[64,K] @ Bw[K,Nfull] + bias
// ---------------------------------------------------------------------------
__global__ void k_mlp(const float* __restrict__ Bw, const float* __restrict__ bias,
                      int K, int Nfull, int phase, float* __restrict__ dout) {
    const float* A = (phase == 0) ? g_pooled : g_hn;
    float* C       = (phase == 0) ? g_h : dout;

    int n0  = blockIdx.x * 64;
    int tid = threadIdx.x;
    int tx = tid & 15, ty = tid >> 4;

    __shared__ float As[64][17];
    __shared__ float Bs[16][64];

    float acc[4][4];
#pragma unroll
    for (int i = 0; i < 4; i++)
#pragma unroll
        for (int j = 0; j < 4; j++) acc[i][j] = 0.0f;

    int ar = tid >> 2, ak = (tid & 3) * 4;
    int bk = tid >> 4, bc4 = (tid & 15) * 4;

    for (int k0 = 0; k0 < K; k0 += 16) {
        __syncthreads();
        float4 av = *(const float4*)(A + (size_t)ar * K + k0 + ak);
        As[ar][ak + 0] = av.x; As[ar][ak + 1] = av.y;
        As[ar][ak + 2] = av.z; As[ar][ak + 3] = av.w;
        float4 bv = *(const float4*)(Bw + (size_t)(k0 + bk) * Nfull + n0 + bc4);
        *(float4*)&Bs[bk][bc4] = bv;
        __syncthreads();
#pragma unroll
        for (int kk = 0; kk < 16; kk++) {
            float a[4], b[4];
#pragma unroll
            for (int i = 0; i < 4; i++) a[i] = As[ty * 4 + i][kk];
#pragma unroll
            for (int j = 0; j < 4; j++) b[j] = Bs[kk][tx * 4 + j];
#pragma unroll
            for (int i = 0; i < 4; i++)
#pragma unroll
                for (int j = 0; j < 4; j++) acc[i][j] = fmaf(a[i], b[j], acc[i][j]);
        }
    }
#pragma unroll
    for (int i = 0; i < 4; i++)
#pragma unroll
        for (int j = 0; j < 4; j++)
            C[(size_t)(ty * 4 + i) * Nfull + n0 + tx * 4 + j] =
                acc[i][j] + bias[n0 + tx * 4 + j];
}

// ---------------------------------------------------------------------------
// 6. BatchNorm (training stats over B=64 rows) + ReLU : g_h -> g_hn
// ---------------------------------------------------------------------------
__global__ void k_bn(const float* __restrict__ gamma, const float* __restrict__ beta) {
    int d = blockIdx.x * blockDim.x + threadIdx.x;  // 0..1023
    float v[NB];
    float s = 0.0f;
#pragma unroll
    for (int r = 0; r < NB; r++) {
        v[r] = g_h[(size_t)r * D1 + d];
        s += v[r];
    }
    float mean = s * (1.0f / NB);
    float q = 0.0f;
#pragma unroll
    for (int r = 0; r < NB; r++) {
        float df = v[r] - mean;
        q = fmaf(df, df, q);
    }
    float var = q * (1.0f / NB);
    float sc = rsqrtf(var + 1e-5f) * gamma[d];
    float bt = beta[d];
#pragma unroll
    for (int r = 0; r < NB; r++)
        g_hn[(size_t)r * D1 + d] = fmaxf(0.0f, fmaf(v[r] - mean, sc, bt));
}

// ---------------------------------------------------------------------------
// launch
// ---------------------------------------------------------------------------
extern "C" void kernel_launch(void* const* d_in, const int* in_sizes, int n_in,
                              void* d_out, int out_size) {
    const float* feats = (const float*)d_in[0];
    const int*   bidx  = (const int*)d_in[1];
    const float* Wc    = (const float*)d_in[2];
    const float* bc    = (const float*)d_in[3];
    const float* W1    = (const float*)d_in[4];
    const float* b1    = (const float*)d_in[5];
    const float* gamma = (const float*)d_in[6];
    const float* beta  = (const float*)d_in[7];
    const float* W2    = (const float*)d_in[8];
    const float* b2    = (const float*)d_in[9];
    int N = in_sizes[1];  // number of points (batch_idx element count)

    k_init<<<(NB * C_CONV + 255) / 256, 256>>>();
    k_hist<<<(N + 255) / 256, 256>>>(bidx, N);
    k_scan<<<1, 64>>>();
    k_scatter<<<(N + 255) / 256, 256>>>(bidx, N);
    k_convert<<<(N + 7) / 8, 256>>>(feats, N);
    k_convw<<<(C_IN * C_CONV) / (256 * 8), 256>>>(Wc);

    int maxTiles = (N + BM - 1) / BM + NB;
    dim3 grid(C_CONV / BN, maxTiles);   // n-blocks fastest -> L2 reuse of A
    k_gemm<<<grid, 256>>>(g_afp16);

    k_exact<<<(NB * C_CONV * 32 + 255) / 256, 256>>>(feats, Wc, bc);

    k_mlp<<<D1 / 64, 256>>>(W1, b1, C_CONV, D1, 0, nullptr);
    k_bn<<<D1 / 256, 256>>>(gamma, beta);
    k_mlp<<<D2 / 64, 256>>>(W2, b2, D1, D2, 1, (float*)d_out);
}